// round 11
// baseline (speedup 1.0000x reference)
#include <cuda_runtime.h>
#include <cstdint>

#define BQ  16
#define HH  512
#define WW  512
#define MM  64
#define NPTS 5
#define NTOT (BQ*HH*WW)      // 4194304
#define TXT  1024            // text blocks (R1-proven geometry)
#define NTHR 256
#define GRID (BQ + TXT)      // 1040 blocks; capacity 148*8=1184 -> single wave

// Scratch (no allocation allowed)
__device__ float g_part[TXT*4];
__device__ float g_box[BQ*3];
__device__ unsigned int g_count;

__device__ __forceinline__ float wredf(float v){
  #pragma unroll
  for (int o = 16; o > 0; o >>= 1) v += __shfl_xor_sync(0xffffffffu, v, o);
  return v;
}
__device__ __forceinline__ double wredd(double v){
  #pragma unroll
  for (int o = 16; o > 0; o >>= 1) v += __shfl_xor_sync(0xffffffffu, v, o);
  return v;
}
__device__ __forceinline__ float clipf(float x, float lo, float hi){
  return fminf(fmaxf(x, lo), hi);
}
__device__ __forceinline__ float sl1(float d){
  d = fabsf(d);
  return (d < 1.0f) ? 0.5f*d*d : d - 0.5f;
}

// R1-proven accumulate (4 logs per float4-pair)
__device__ __forceinline__ void acc4(float4 pv, float4 tv,
                                     float& sb, float& spt, float& sp, float& st){
  float pa[4] = {pv.x, pv.y, pv.z, pv.w};
  float ta[4] = {tv.x, tv.y, tv.z, tv.w};
  #pragma unroll
  for (int c = 0; c < 4; c++){
    float pp = pa[c], tt = ta[c];
    sb  -= __logf(tt > 0.5f ? pp : 1.0f - pp);   // t is exactly 0 or 1
    spt  = fmaf(pp, tt, spt);
    sp  += pp;
    st  += tt;
  }
}

__global__ void __launch_bounds__(NTHR)
fused_kernel(const float4* __restrict__ p4,        // text_map
             const float4* __restrict__ t4,        // target_text_map
             const float*  __restrict__ bbox,      // [B,4,H,W]
             const float*  __restrict__ conf,      // [B,1,H,W]
             const float*  __restrict__ tboxes,    // [B,M,5]
             const int*    __restrict__ bmask,     // [B,M]
             float*        __restrict__ out){
  const int tid = threadIdx.x;
  const int w = tid >> 5, l = tid & 31;

  if (blockIdx.x >= BQ){
    // ------- text BCE + dice: R1's exact proven 3.0 TB/s loop shape ---------
    const int tb   = blockIdx.x - BQ;              // 0..TXT-1
    const int base = tb * NTHR + tid;
    const int S    = TXT * NTHR;                   // 262144; n4 = 4*S
    float sb = 0.f, spt = 0.f, sp = 0.f, st = 0.f;
    #pragma unroll 1
    for (int k = 0; k < 4; k++){
      int i = base + k*S;
      float4 pv = p4[i];
      float4 tv = t4[i];
      acc4(pv, tv, sb, spt, sp, st);
    }
    sb = wredf(sb); spt = wredf(spt); sp = wredf(sp); st = wredf(st);
    __shared__ float sh[4][NTHR/32];
    if (l == 0){ sh[0][w]=sb; sh[1][w]=spt; sh[2][w]=sp; sh[3][w]=st; }
    __syncthreads();
    if (tid == 0){
      float a=0.f,b=0.f,c=0.f,d=0.f;
      #pragma unroll
      for (int i = 0; i < NTHR/32; i++){ a+=sh[0][i]; b+=sh[1][i]; c+=sh[2][i]; d+=sh[3][i]; }
      g_part[tb*4+0]=a; g_part[tb*4+1]=b;
      g_part[tb*4+2]=c; g_part[tb*4+3]=d;
    }
  } else {
    // -------- box/conf losses for batch b (scheduled first, overlaps) -------
    const int b = blockIdx.x;
    float s0=0.f, s1=0.f, s2=0.f, s3=0.f, s4=0.f;
    for (int i = tid; i < MM*NPTS; i += NTHR){
      int m  = i / NPTS;
      int pt = i % NPTS;
      const float* tbm = tboxes + ((size_t)b*MM + m)*5;
      float tconf = tbm[0];
      float nx1 = clipf(tbm[1] * (1.0f/512.0f), 0.f, 1.f);
      float ny1 = clipf(tbm[2] * (1.0f/512.0f), 0.f, 1.f);
      float nx2 = clipf(tbm[3] * (1.0f/512.0f), 0.f, 1.f);
      float ny2 = clipf(tbm[4] * (1.0f/512.0f), 0.f, 1.f);
      int x1p = min(max((int)(nx1 * 512.0f), 0), WW-1);
      int y1p = min(max((int)(ny1 * 512.0f), 0), HH-1);
      int x2p = min(max((int)(nx2 * 512.0f), 0), WW-1);
      int y2p = min(max((int)(ny2 * 512.0f), 0), HH-1);
      int cy = (y1p + y2p) >> 1;
      int cx = (x1p + x2p) >> 1;

      int yy, xx;
      switch (pt){
        case 0: yy = cy;  xx = cx;  break;
        case 1: yy = y1p; xx = x1p; break;
        case 2: yy = y1p; xx = x2p; break;
        case 3: yy = y2p; xx = x1p; break;
        default:yy = y2p; xx = x2p; break;
      }

      size_t hw  = (size_t)HH*WW;
      size_t off = (size_t)yy*WW + xx;
      const float* bb = bbox + (size_t)b*4*hw;
      float c0 = bb[off];
      float c1 = bb[hw   + off];
      float c2 = bb[2*hw + off];
      float c3 = bb[3*hw + off];
      float cp = conf[(size_t)b*hw + off];

      float px1 = clipf(c0, 0.00f, 0.99f);
      float py1 = clipf(c1, 0.00f, 0.99f);
      float px2 = clipf(c2, 0.01f, 1.00f);
      float py2 = clipf(c3, 0.01f, 1.00f);
      float bx1 = fminf(px1, px2), bx2 = fmaxf(px1, px2);
      float by1 = fminf(py1, py2), by2 = fmaxf(py1, py2);

      float pa = (bx2 - bx1) * (by2 - by1);
      float ta = (nx2 - nx1) * (ny2 - ny1);
      float ix1 = fmaxf(bx1, nx1), iy1 = fmaxf(by1, ny1);
      float ix2 = fminf(bx2, nx2), iy2 = fminf(by2, ny2);
      float inter = fmaxf(ix2 - ix1, 0.f) * fmaxf(iy2 - iy1, 0.f);
      float uni = pa + ta - inter;
      float iou = inter / (uni + 1e-6f);
      float ex1 = fminf(bx1, nx1), ey1 = fminf(by1, ny1);
      float ex2 = fmaxf(bx2, nx2), ey2 = fmaxf(by2, ny2);
      float enc = (ex2 - ex1) * (ey2 - ey1);
      float giou = iou - (enc - uni) / (enc + 1e-6f);

      float iou_pt  = -__logf(iou + 1e-6f);
      float giou_pt = 1.0f - giou;
      float l1_pt   = 0.25f * (sl1(bx1-nx1) + sl1(by1-ny1) + sl1(bx2-nx2) + sl1(by2-ny2));
      float bce     = -(tconf*__logf(cp) + (1.0f - tconf)*__logf(1.0f - cp));

      float mk = (float)bmask[b*MM + m];
      s0 = fmaf(iou_pt,  mk, s0);
      s1 = fmaf(l1_pt,   mk, s1);
      s2 = fmaf(giou_pt, mk, s2);
      s3 = fmaf(bce,     mk, s3);
      s4 += mk;
    }
    s0 = wredf(s0); s1 = wredf(s1); s2 = wredf(s2); s3 = wredf(s3); s4 = wredf(s4);
    __shared__ float shb[5][NTHR/32];
    if (l == 0){ shb[0][w]=s0; shb[1][w]=s1; shb[2][w]=s2; shb[3][w]=s3; shb[4][w]=s4; }
    __syncthreads();
    if (tid == 0){
      float a0=0,a1=0,a2=0,a3=0,a4=0;
      #pragma unroll
      for (int i = 0; i < NTHR/32; i++){
        a0+=shb[0][i]; a1+=shb[1][i]; a2+=shb[2][i]; a3+=shb[3][i]; a4+=shb[4][i];
      }
      float cnt = fmaxf(a4, 1.0f);
      g_box[b*3+0] = 0.5f*(a0/cnt) + 0.3f*(a1/cnt) + 0.2f*(a2/cnt);
      g_box[b*3+1] = a3/cnt;
      g_box[b*3+2] = (a4 > 0.f) ? 1.0f : 0.0f;
    }
  }

  // ---------- last-block combine (only tid 0 fences + counts) ---------------
  __shared__ bool isLast;
  if (tid == 0){
    __threadfence();
    unsigned int v = atomicAdd(&g_count, 1u);
    isLast = (v == (unsigned int)(GRID - 1));
    if (isLast) __threadfence();
  }
  __syncthreads();
  if (!isLast) return;

  // 4 independent float4 loads per iteration -> latency-parallel tail
  double s0=0.0, s1=0.0, s2=0.0, s3=0.0;
  const float4* gp4 = (const float4*)g_part;       // [TXT] of {bce,pt,p,t}
  #pragma unroll 1
  for (int i = tid; i < TXT; i += NTHR){
    float4 v = gp4[i];
    s0 += (double)v.x; s1 += (double)v.y; s2 += (double)v.z; s3 += (double)v.w;
  }
  s0 = wredd(s0); s1 = wredd(s1); s2 = wredd(s2); s3 = wredd(s3);
  __shared__ double shd[4][NTHR/32];
  if (l == 0){ shd[0][w]=s0; shd[1][w]=s1; shd[2][w]=s2; shd[3][w]=s3; }
  __syncthreads();
  if (tid == 0){
    double Sb=0, Spt=0, Sp=0, St=0;
    #pragma unroll
    for (int i = 0; i < NTHR/32; i++){ Sb+=shd[0][i]; Spt+=shd[1][i]; Sp+=shd[2][i]; St+=shd[3][i]; }
    float bce_mean = (float)(Sb / (double)NTOT);
    float dice = (float)((2.0*Spt + 1e-5) / (Sp + St + 1e-5));
    float text_loss = 0.5f*bce_mean + 0.5f*(1.0f - dice);

    float nvalid = 0.f, sc = 0.f, scf = 0.f;
    #pragma unroll
    for (int b = 0; b < BQ; b++){
      float v = g_box[b*3+2];
      nvalid += v;
      sc  += g_box[b*3+0] * v;
      scf += g_box[b*3+1] * v;
    }
    nvalid = fmaxf(nvalid, 1.0f);
    out[0] = text_loss + 20.0f*(sc/nvalid) + 0.5f*(scf/nvalid);
    g_count = 0;   // reset for next graph replay
  }
}

extern "C" void kernel_launch(void* const* d_in, const int* in_sizes, int n_in,
                              void* d_out, int out_size){
  const float* text_map        = (const float*)d_in[0];
  const float* confidence      = (const float*)d_in[1];
  const float* bbox_coords     = (const float*)d_in[2];
  const float* target_text_map = (const float*)d_in[3];
  const float* target_boxes    = (const float*)d_in[4];
  const int*   box_mask        = (const int*)  d_in[5];

  fused_kernel<<<GRID, NTHR>>>((const float4*)text_map,
                               (const float4*)target_text_map,
                               bbox_coords, confidence, target_boxes, box_mask,
                               (float*)d_out);
}

// round 13
// speedup vs baseline: 1.2055x; 1.2055x over previous
#include <cuda_runtime.h>
#include <cstdint>

#define BQ  16
#define HH  512
#define WW  512
#define MM  64
#define NPTS 5
#define NTOT (BQ*HH*WW)      // 4194304
#define TXT  512             // text blocks (R5-proven)
#define NTHR 256
#define GRID (BQ + TXT)      // 528 blocks, single wave

// Scratch (no allocation allowed)
__device__ float g_part[TXT*4];
__device__ float g_box[BQ*3];
__device__ unsigned int g_count;

__device__ __forceinline__ float wredf(float v){
  #pragma unroll
  for (int o = 16; o > 0; o >>= 1) v += __shfl_xor_sync(0xffffffffu, v, o);
  return v;
}
__device__ __forceinline__ double wredd(double v){
  #pragma unroll
  for (int o = 16; o > 0; o >>= 1) v += __shfl_xor_sync(0xffffffffu, v, o);
  return v;
}
__device__ __forceinline__ float clipf(float x, float lo, float hi){
  return fminf(fmaxf(x, lo), hi);
}
__device__ __forceinline__ float sl1(float d){
  d = fabsf(d);
  return (d < 1.0f) ? 0.5f*d*d : d - 0.5f;
}

// Blackwell 256-bit global load (LDG.E.256): half the requests, 2x bytes each.
__device__ __forceinline__ void ldg8(const float* p, float* v){
  asm volatile("ld.global.nc.v8.f32 {%0,%1,%2,%3,%4,%5,%6,%7}, [%8];"
               : "=f"(v[0]), "=f"(v[1]), "=f"(v[2]), "=f"(v[3]),
                 "=f"(v[4]), "=f"(v[5]), "=f"(v[6]), "=f"(v[7])
               : "l"(p));
}

// R1-proven accumulate (4 logs per float4-pair), applied to 8 lanes.
__device__ __forceinline__ void acc8(const float* pv, const float* tv,
                                     float& sb, float& spt, float& sp, float& st){
  #pragma unroll
  for (int c = 0; c < 8; c++){
    float pp = pv[c], tt = tv[c];
    sb  -= __logf(tt > 0.5f ? pp : 1.0f - pp);   // t is exactly 0 or 1
    spt  = fmaf(pp, tt, spt);
    sp  += pp;
    st  += tt;
  }
}

__global__ void __launch_bounds__(NTHR)
fused_kernel(const float* __restrict__ pf,         // text_map
             const float* __restrict__ tf,         // target_text_map
             const float* __restrict__ bbox,       // [B,4,H,W]
             const float* __restrict__ conf,       // [B,1,H,W]
             const float* __restrict__ tboxes,     // [B,M,5]
             const int*   __restrict__ bmask,      // [B,M]
             float*       __restrict__ out){
  const int tid = threadIdx.x;
  const int w = tid >> 5, l = tid & 31;

  if (blockIdx.x >= BQ){
    // ------- text BCE + dice: R5 structure, 256-bit loads -------------------
    const int tb    = blockIdx.x - BQ;             // 0..TXT-1
    const int base8 = tb * NTHR + tid;             // float8 index
    const int S8    = TXT * NTHR;                  // 131072; total f8 = 4*S8
    float sb = 0.f, spt = 0.f, sp = 0.f, st = 0.f;
    #pragma unroll 1
    for (int k = 0; k < 2; k++){
      int i0 = (base8 + (2*k  )*S8) * 8;
      int i1 = (base8 + (2*k+1)*S8) * 8;
      float a0[8], b0[8], a1[8], b1[8];
      ldg8(pf + i0, a0);
      ldg8(tf + i0, b0);
      ldg8(pf + i1, a1);
      ldg8(tf + i1, b1);
      acc8(a0, b0, sb, spt, sp, st);
      acc8(a1, b1, sb, spt, sp, st);
    }
    sb = wredf(sb); spt = wredf(spt); sp = wredf(sp); st = wredf(st);
    __shared__ float sh[4][NTHR/32];
    if (l == 0){ sh[0][w]=sb; sh[1][w]=spt; sh[2][w]=sp; sh[3][w]=st; }
    __syncthreads();
    if (tid == 0){
      float a=0.f,b=0.f,c=0.f,d=0.f;
      #pragma unroll
      for (int i = 0; i < NTHR/32; i++){ a+=sh[0][i]; b+=sh[1][i]; c+=sh[2][i]; d+=sh[3][i]; }
      g_part[tb*4+0]=a; g_part[tb*4+1]=b;
      g_part[tb*4+2]=c; g_part[tb*4+3]=d;
    }
  } else {
    // -------- box/conf losses for batch b (scheduled first, overlaps) -------
    const int b = blockIdx.x;
    float s0=0.f, s1=0.f, s2=0.f, s3=0.f, s4=0.f;
    for (int i = tid; i < MM*NPTS; i += NTHR){
      int m  = i / NPTS;
      int pt = i % NPTS;
      const float* tbm = tboxes + ((size_t)b*MM + m)*5;
      float tconf = tbm[0];
      float nx1 = clipf(tbm[1] * (1.0f/512.0f), 0.f, 1.f);
      float ny1 = clipf(tbm[2] * (1.0f/512.0f), 0.f, 1.f);
      float nx2 = clipf(tbm[3] * (1.0f/512.0f), 0.f, 1.f);
      float ny2 = clipf(tbm[4] * (1.0f/512.0f), 0.f, 1.f);
      int x1p = min(max((int)(nx1 * 512.0f), 0), WW-1);
      int y1p = min(max((int)(ny1 * 512.0f), 0), HH-1);
      int x2p = min(max((int)(nx2 * 512.0f), 0), WW-1);
      int y2p = min(max((int)(ny2 * 512.0f), 0), HH-1);
      int cy = (y1p + y2p) >> 1;
      int cx = (x1p + x2p) >> 1;

      int yy, xx;
      switch (pt){
        case 0: yy = cy;  xx = cx;  break;
        case 1: yy = y1p; xx = x1p; break;
        case 2: yy = y1p; xx = x2p; break;
        case 3: yy = y2p; xx = x1p; break;
        default:yy = y2p; xx = x2p; break;
      }

      size_t hw  = (size_t)HH*WW;
      size_t off = (size_t)yy*WW + xx;
      const float* bb = bbox + (size_t)b*4*hw;
      float c0 = bb[off];
      float c1 = bb[hw   + off];
      float c2 = bb[2*hw + off];
      float c3 = bb[3*hw + off];
      float cp = conf[(size_t)b*hw + off];

      float px1 = clipf(c0, 0.00f, 0.99f);
      float py1 = clipf(c1, 0.00f, 0.99f);
      float px2 = clipf(c2, 0.01f, 1.00f);
      float py2 = clipf(c3, 0.01f, 1.00f);
      float bx1 = fminf(px1, px2), bx2 = fmaxf(px1, px2);
      float by1 = fminf(py1, py2), by2 = fmaxf(py1, py2);

      float pa = (bx2 - bx1) * (by2 - by1);
      float ta = (nx2 - nx1) * (ny2 - ny1);
      float ix1 = fmaxf(bx1, nx1), iy1 = fmaxf(by1, ny1);
      float ix2 = fminf(bx2, nx2), iy2 = fminf(by2, ny2);
      float inter = fmaxf(ix2 - ix1, 0.f) * fmaxf(iy2 - iy1, 0.f);
      float uni = pa + ta - inter;
      float iou = inter / (uni + 1e-6f);
      float ex1 = fminf(bx1, nx1), ey1 = fminf(by1, ny1);
      float ex2 = fmaxf(bx2, nx2), ey2 = fmaxf(by2, ny2);
      float enc = (ex2 - ex1) * (ey2 - ey1);
      float giou = iou - (enc - uni) / (enc + 1e-6f);

      float iou_pt  = -__logf(iou + 1e-6f);
      float giou_pt = 1.0f - giou;
      float l1_pt   = 0.25f * (sl1(bx1-nx1) + sl1(by1-ny1) + sl1(bx2-nx2) + sl1(by2-ny2));
      float bce     = -(tconf*__logf(cp) + (1.0f - tconf)*__logf(1.0f - cp));

      float mk = (float)bmask[b*MM + m];
      s0 = fmaf(iou_pt,  mk, s0);
      s1 = fmaf(l1_pt,   mk, s1);
      s2 = fmaf(giou_pt, mk, s2);
      s3 = fmaf(bce,     mk, s3);
      s4 += mk;
    }
    s0 = wredf(s0); s1 = wredf(s1); s2 = wredf(s2); s3 = wredf(s3); s4 = wredf(s4);
    __shared__ float shb[5][NTHR/32];
    if (l == 0){ shb[0][w]=s0; shb[1][w]=s1; shb[2][w]=s2; shb[3][w]=s3; shb[4][w]=s4; }
    __syncthreads();
    if (tid == 0){
      float a0=0,a1=0,a2=0,a3=0,a4=0;
      #pragma unroll
      for (int i = 0; i < NTHR/32; i++){
        a0+=shb[0][i]; a1+=shb[1][i]; a2+=shb[2][i]; a3+=shb[3][i]; a4+=shb[4][i];
      }
      float cnt = fmaxf(a4, 1.0f);
      g_box[b*3+0] = 0.5f*(a0/cnt) + 0.3f*(a1/cnt) + 0.2f*(a2/cnt);
      g_box[b*3+1] = a3/cnt;
      g_box[b*3+2] = (a4 > 0.f) ? 1.0f : 0.0f;
    }
  }

  // ---------- last-block combine (only tid 0 fences + counts) ---------------
  __shared__ bool isLast;
  if (tid == 0){
    __threadfence();
    unsigned int v = atomicAdd(&g_count, 1u);
    isLast = (v == (unsigned int)(GRID - 1));
    if (isLast) __threadfence();
  }
  __syncthreads();
  if (!isLast) return;

  double s0=0.0, s1=0.0, s2=0.0, s3=0.0;
  const float4* gp4 = (const float4*)g_part;       // [TXT] of {bce,pt,p,t}
  #pragma unroll 1
  for (int i = tid; i < TXT; i += NTHR){
    float4 v = gp4[i];
    s0 += (double)v.x; s1 += (double)v.y; s2 += (double)v.z; s3 += (double)v.w;
  }
  s0 = wredd(s0); s1 = wredd(s1); s2 = wredd(s2); s3 = wredd(s3);
  __shared__ double shd[4][NTHR/32];
  if (l == 0){ shd[0][w]=s0; shd[1][w]=s1; shd[2][w]=s2; shd[3][w]=s3; }
  __syncthreads();
  if (tid == 0){
    double Sb=0, Spt=0, Sp=0, St=0;
    #pragma unroll
    for (int i = 0; i < NTHR/32; i++){ Sb+=shd[0][i]; Spt+=shd[1][i]; Sp+=shd[2][i]; St+=shd[3][i]; }
    float bce_mean = (float)(Sb / (double)NTOT);
    float dice = (float)((2.0*Spt + 1e-5) / (Sp + St + 1e-5));
    float text_loss = 0.5f*bce_mean + 0.5f*(1.0f - dice);

    float nvalid = 0.f, sc = 0.f, scf = 0.f;
    #pragma unroll
    for (int b = 0; b < BQ; b++){
      float v = g_box[b*3+2];
      nvalid += v;
      sc  += g_box[b*3+0] * v;
      scf += g_box[b*3+1] * v;
    }
    nvalid = fmaxf(nvalid, 1.0f);
    out[0] = text_loss + 20.0f*(sc/nvalid) + 0.5f*(scf/nvalid);
    g_count = 0;   // reset for next graph replay
  }
}

extern "C" void kernel_launch(void* const* d_in, const int* in_sizes, int n_in,
                              void* d_out, int out_size){
  const float* text_map        = (const float*)d_in[0];
  const float* confidence      = (const float*)d_in[1];
  const float* bbox_coords     = (const float*)d_in[2];
  const float* target_text_map = (const float*)d_in[3];
  const float* target_boxes    = (const float*)d_in[4];
  const int*   box_mask        = (const int*)  d_in[5];

  fused_kernel<<<GRID, NTHR>>>(text_map, target_text_map,
                               bbox_coords, confidence, target_boxes, box_mask,
                               (float*)d_out);
}

// round 16
// speedup vs baseline: 1.2644x; 1.0489x over previous
#include <cuda_runtime.h>
#include <cstdint>

#define BQ  16
#define HH  512
#define WW  512
#define MM  64
#define NPTS 5
#define NTOT (BQ*HH*WW)      // 4194304
#define TXT  512             // text blocks (R5-proven)
#define NTHR 256
#define GRID (BQ + TXT)      // 528 blocks, single wave
#define NIT  8               // float4-pairs per thread
#define DIST 3               // pipeline distance (3 pair-loads in flight)

// Scratch (no allocation allowed)
__device__ float g_part[TXT*4];
__device__ float g_box[BQ*3];
__device__ unsigned int g_count;

__device__ __forceinline__ float wredf(float v){
  #pragma unroll
  for (int o = 16; o > 0; o >>= 1) v += __shfl_xor_sync(0xffffffffu, v, o);
  return v;
}
__device__ __forceinline__ double wredd(double v){
  #pragma unroll
  for (int o = 16; o > 0; o >>= 1) v += __shfl_xor_sync(0xffffffffu, v, o);
  return v;
}
__device__ __forceinline__ float clipf(float x, float lo, float hi){
  return fminf(fmaxf(x, lo), hi);
}
__device__ __forceinline__ float sl1(float d){
  d = fabsf(d);
  return (d < 1.0f) ? 0.5f*d*d : d - 0.5f;
}

__device__ __forceinline__ void acc4(float4 pv, float4 tv,
                                     float& sb, float& spt, float& sp, float& st){
  float pa[4] = {pv.x, pv.y, pv.z, pv.w};
  float ta[4] = {tv.x, tv.y, tv.z, tv.w};
  #pragma unroll
  for (int c = 0; c < 4; c++){
    float pp = pa[c], tt = ta[c];
    sb  -= __logf(tt > 0.5f ? pp : 1.0f - pp);   // t is exactly 0 or 1
    spt  = fmaf(pp, tt, spt);
    sp  += pp;
    st  += tt;
  }
}

__global__ void __launch_bounds__(NTHR)
fused_kernel(const float4* __restrict__ p4,        // text_map
             const float4* __restrict__ t4,        // target_text_map
             const float*  __restrict__ bbox,      // [B,4,H,W]
             const float*  __restrict__ conf,      // [B,1,H,W]
             const float*  __restrict__ tboxes,    // [B,M,5]
             const int*    __restrict__ bmask,     // [B,M]
             float*        __restrict__ out){
  const int tid = threadIdx.x;
  const int w = tid >> 5, l = tid & 31;

  if (blockIdx.x >= BQ){
    // -- text BCE + dice: distance-3 software pipeline (deps force MLP>=6) ---
    const int tb   = blockIdx.x - BQ;              // 0..TXT-1
    const int base = tb * NTHR + tid;
    const int S    = TXT * NTHR;                   // 131072; n4 = 8*S

    float4 pbuf[DIST+1], tbuf[DIST+1];
    // prefetch pairs 0..DIST-1
    #pragma unroll
    for (int k = 0; k < DIST; k++){
      pbuf[k] = p4[base + k*S];
      tbuf[k] = t4[base + k*S];
    }

    float sb = 0.f, spt = 0.f, sp = 0.f, st = 0.f;
    #pragma unroll
    for (int k = 0; k < NIT; k++){
      int slot  = k % (DIST+1);
      int fslot = (k + DIST) % (DIST+1);
      if (k + DIST < NIT){
        pbuf[fslot] = p4[base + (k+DIST)*S];
        tbuf[fslot] = t4[base + (k+DIST)*S];
      }
      acc4(pbuf[slot], tbuf[slot], sb, spt, sp, st);
    }

    sb = wredf(sb); spt = wredf(spt); sp = wredf(sp); st = wredf(st);
    __shared__ float sh[4][NTHR/32];
    if (l == 0){ sh[0][w]=sb; sh[1][w]=spt; sh[2][w]=sp; sh[3][w]=st; }
    __syncthreads();
    if (tid == 0){
      float a=0.f,b=0.f,c=0.f,d=0.f;
      #pragma unroll
      for (int i = 0; i < NTHR/32; i++){ a+=sh[0][i]; b+=sh[1][i]; c+=sh[2][i]; d+=sh[3][i]; }
      g_part[tb*4+0]=a; g_part[tb*4+1]=b;
      g_part[tb*4+2]=c; g_part[tb*4+3]=d;
    }
  } else {
    // -------- box/conf losses for batch b (scheduled first, overlaps) -------
    const int b = blockIdx.x;
    float s0=0.f, s1=0.f, s2=0.f, s3=0.f, s4=0.f;
    for (int i = tid; i < MM*NPTS; i += NTHR){
      int m  = i / NPTS;
      int pt = i % NPTS;
      const float* tbm = tboxes + ((size_t)b*MM + m)*5;
      float tconf = tbm[0];
      float nx1 = clipf(tbm[1] * (1.0f/512.0f), 0.f, 1.f);
      float ny1 = clipf(tbm[2] * (1.0f/512.0f), 0.f, 1.f);
      float nx2 = clipf(tbm[3] * (1.0f/512.0f), 0.f, 1.f);
      float ny2 = clipf(tbm[4] * (1.0f/512.0f), 0.f, 1.f);
      int x1p = min(max((int)(nx1 * 512.0f), 0), WW-1);
      int y1p = min(max((int)(ny1 * 512.0f), 0), HH-1);
      int x2p = min(max((int)(nx2 * 512.0f), 0), WW-1);
      int y2p = min(max((int)(ny2 * 512.0f), 0), HH-1);
      int cy = (y1p + y2p) >> 1;
      int cx = (x1p + x2p) >> 1;

      int yy, xx;
      switch (pt){
        case 0: yy = cy;  xx = cx;  break;
        case 1: yy = y1p; xx = x1p; break;
        case 2: yy = y1p; xx = x2p; break;
        case 3: yy = y2p; xx = x1p; break;
        default:yy = y2p; xx = x2p; break;
      }

      size_t hw  = (size_t)HH*WW;
      size_t off = (size_t)yy*WW + xx;
      const float* bb = bbox + (size_t)b*4*hw;
      float c0 = bb[off];
      float c1 = bb[hw   + off];
      float c2 = bb[2*hw + off];
      float c3 = bb[3*hw + off];
      float cp = conf[(size_t)b*hw + off];

      float px1 = clipf(c0, 0.00f, 0.99f);
      float py1 = clipf(c1, 0.00f, 0.99f);
      float px2 = clipf(c2, 0.01f, 1.00f);
      float py2 = clipf(c3, 0.01f, 1.00f);
      float bx1 = fminf(px1, px2), bx2 = fmaxf(px1, px2);
      float by1 = fminf(py1, py2), by2 = fmaxf(py1, py2);

      float pa = (bx2 - bx1) * (by2 - by1);
      float ta = (nx2 - nx1) * (ny2 - ny1);
      float ix1 = fmaxf(bx1, nx1), iy1 = fmaxf(by1, ny1);
      float ix2 = fminf(bx2, nx2), iy2 = fminf(by2, ny2);
      float inter = fmaxf(ix2 - ix1, 0.f) * fmaxf(iy2 - iy1, 0.f);
      float uni = pa + ta - inter;
      float iou = inter / (uni + 1e-6f);
      float ex1 = fminf(bx1, nx1), ey1 = fminf(by1, ny1);
      float ex2 = fmaxf(bx2, nx2), ey2 = fmaxf(by2, ny2);
      float enc = (ex2 - ex1) * (ey2 - ey1);
      float giou = iou - (enc - uni) / (enc + 1e-6f);

      float iou_pt  = -__logf(iou + 1e-6f);
      float giou_pt = 1.0f - giou;
      float l1_pt   = 0.25f * (sl1(bx1-nx1) + sl1(by1-ny1) + sl1(bx2-nx2) + sl1(by2-ny2));
      float bce     = -(tconf*__logf(cp) + (1.0f - tconf)*__logf(1.0f - cp));

      float mk = (float)bmask[b*MM + m];
      s0 = fmaf(iou_pt,  mk, s0);
      s1 = fmaf(l1_pt,   mk, s1);
      s2 = fmaf(giou_pt, mk, s2);
      s3 = fmaf(bce,     mk, s3);
      s4 += mk;
    }
    s0 = wredf(s0); s1 = wredf(s1); s2 = wredf(s2); s3 = wredf(s3); s4 = wredf(s4);
    __shared__ float shb[5][NTHR/32];
    if (l == 0){ shb[0][w]=s0; shb[1][w]=s1; shb[2][w]=s2; shb[3][w]=s3; shb[4][w]=s4; }
    __syncthreads();
    if (tid == 0){
      float a0=0,a1=0,a2=0,a3=0,a4=0;
      #pragma unroll
      for (int i = 0; i < NTHR/32; i++){
        a0+=shb[0][i]; a1+=shb[1][i]; a2+=shb[2][i]; a3+=shb[3][i]; a4+=shb[4][i];
      }
      float cnt = fmaxf(a4, 1.0f);
      g_box[b*3+0] = 0.5f*(a0/cnt) + 0.3f*(a1/cnt) + 0.2f*(a2/cnt);
      g_box[b*3+1] = a3/cnt;
      g_box[b*3+2] = (a4 > 0.f) ? 1.0f : 0.0f;
    }
  }

  // ---------- last-block combine (only tid 0 fences + counts) ---------------
  __shared__ bool isLast;
  if (tid == 0){
    __threadfence();
    unsigned int v = atomicAdd(&g_count, 1u);
    isLast = (v == (unsigned int)(GRID - 1));
    if (isLast) __threadfence();
  }
  __syncthreads();
  if (!isLast) return;

  double s0=0.0, s1=0.0, s2=0.0, s3=0.0;
  const float4* gp4 = (const float4*)g_part;       // [TXT] of {bce,pt,p,t}
  #pragma unroll 1
  for (int i = tid; i < TXT; i += NTHR){
    float4 v = gp4[i];
    s0 += (double)v.x; s1 += (double)v.y; s2 += (double)v.z; s3 += (double)v.w;
  }
  s0 = wredd(s0); s1 = wredd(s1); s2 = wredd(s2); s3 = wredd(s3);
  __shared__ double shd[4][NTHR/32];
  if (l == 0){ shd[0][w]=s0; shd[1][w]=s1; shd[2][w]=s2; shd[3][w]=s3; }
  __syncthreads();
  if (tid == 0){
    double Sb=0, Spt=0, Sp=0, St=0;
    #pragma unroll
    for (int i = 0; i < NTHR/32; i++){ Sb+=shd[0][i]; Spt+=shd[1][i]; Sp+=shd[2][i]; St+=shd[3][i]; }
    float bce_mean = (float)(Sb / (double)NTOT);
    float dice = (float)((2.0*Spt + 1e-5) / (Sp + St + 1e-5));
    float text_loss = 0.5f*bce_mean + 0.5f*(1.0f - dice);

    float nvalid = 0.f, sc = 0.f, scf = 0.f;
    #pragma unroll
    for (int b = 0; b < BQ; b++){
      float v = g_box[b*3+2];
      nvalid += v;
      sc  += g_box[b*3+0] * v;
      scf += g_box[b*3+1] * v;
    }
    nvalid = fmaxf(nvalid, 1.0f);
    out[0] = text_loss + 20.0f*(sc/nvalid) + 0.5f*(scf/nvalid);
    g_count = 0;   // reset for next graph replay
  }
}

extern "C" void kernel_launch(void* const* d_in, const int* in_sizes, int n_in,
                              void* d_out, int out_size){
  const float* text_map        = (const float*)d_in[0];
  const float* confidence      = (const float*)d_in[1];
  const float* bbox_coords     = (const float*)d_in[2];
  const float* target_text_map = (const float*)d_in[3];
  const float* target_boxes    = (const float*)d_in[4];
  const int*   box_mask        = (const int*)  d_in[5];

  fused_kernel<<<GRID, NTHR>>>((const float4*)text_map,
                               (const float4*)target_text_map,
                               bbox_coords, confidence, target_boxes, box_mask,
                               (float*)d_out);
}